// round 4
// baseline (speedup 1.0000x reference)
#include <cuda_runtime.h>
#include <cuda_bf16.h>

// CollisionRegularizer: mean over (B,N,N) of relu(R - dist)^2, diagonal masked.
// B=2, N=8192, xyz float32 (B,N,3). Output: 1 float (the mean).
//
// R3 changes vs R2 (39.0us):
//  - Fused final reduction (last-block ticket) -> no second kernel (-5.4us tax).
//  - t = R - d emitted as FFMA-imm (rt 1 on fma pipe) instead of FADD (rt 2).
//  - LDS.128 j-tile loads (2 packed pairs per load) + unroll.
// Retained: triangular tile-pairs, branchless sqrt.approx(0)=0 diagonal trick,
// f32x2 packed distance math, negated SoA j-tile in shared.

#define RADIUS 0.1f
#define NPTS   8192
#define NBATCH 2
#define TILE   512
#define THREADS 128
#define MI     4                              // i-points per thread
#define NTILES (NPTS / TILE)                  // 16
#define NPAIRT (NTILES * (NTILES + 1) / 2)    // 136 tile-pairs per batch
#define NPART  (NBATCH * NPAIRT)              // 272 blocks / partials

typedef unsigned long long u64;

__device__ __forceinline__ u64 pack2(float lo, float hi) {
    u64 r; asm("mov.b64 %0, {%1, %2};" : "=l"(r) : "f"(lo), "f"(hi)); return r;
}
__device__ __forceinline__ void unpack2(u64 v, float& lo, float& hi) {
    asm("mov.b64 {%0, %1}, %2;" : "=f"(lo), "=f"(hi) : "l"(v));
}
__device__ __forceinline__ u64 add2(u64 a, u64 b) {
    u64 r; asm("add.rn.f32x2 %0, %1, %2;" : "=l"(r) : "l"(a), "l"(b)); return r;
}
__device__ __forceinline__ u64 mul2(u64 a, u64 b) {
    u64 r; asm("mul.rn.f32x2 %0, %1, %2;" : "=l"(r) : "l"(a), "l"(b)); return r;
}
__device__ __forceinline__ u64 fma2(u64 a, u64 b, u64 c) {
    u64 r; asm("fma.rn.f32x2 %0, %1, %2, %3;" : "=l"(r) : "l"(a), "l"(b), "l"(c)); return r;
}
__device__ __forceinline__ float sqrt_approx(float x) {
    float r; asm("sqrt.approx.f32 %0, %1;" : "=f"(r) : "f"(x)); return r;
}
// t = R - d as FFMA with immediate multiplier (-1.0f): rt_SMSP=1 vs FADD's 2.
__device__ __forceinline__ float r_minus(float d, float R) {
    float r; asm("fma.rn.f32 %0, %1, 0fBF800000, %2;" : "=f"(r) : "f"(d), "f"(R)); return r;
}

__device__ float        g_part[NPART];
__device__ unsigned int g_done = 0;

__global__ __launch_bounds__(THREADS)
void collreg_kernel(const float* __restrict__ xyz, float* __restrict__ out) {
    __shared__ __align__(16) float sx[TILE];
    __shared__ __align__(16) float sy[TILE];
    __shared__ __align__(16) float sz[TILE];
    __shared__ float red[THREADS];
    __shared__ bool  is_last;

    const int tid = threadIdx.x;
    const int b   = blockIdx.y;

    // Decode linear tile-pair index -> (ti, tj), tj >= ti.
    int ti = 0, rem = blockIdx.x;
    while (rem >= NTILES - ti) { rem -= NTILES - ti; ti++; }
    const int tj = ti + rem;

    const float* base = xyz + (size_t)b * NPTS * 3;

    // j tile, negated, SoA.
    for (int t = tid; t < TILE; t += THREADS) {
        const int j = tj * TILE + t;
        sx[t] = -base[j * 3 + 0];
        sy[t] = -base[j * 3 + 1];
        sz[t] = -base[j * 3 + 2];
    }
    __syncthreads();

    const float R = RADIUS;

    u64 xip[MI], yip[MI], zip[MI];
    float acc0[MI], acc1[MI];
#pragma unroll
    for (int m = 0; m < MI; m++) {
        const int i = ti * TILE + tid + m * THREADS;
        const float x = base[i * 3 + 0];
        const float y = base[i * 3 + 1];
        const float z = base[i * 3 + 2];
        xip[m] = pack2(x, x);
        yip[m] = pack2(y, y);
        zip[m] = pack2(z, z);
        acc0[m] = 0.0f;
        acc1[m] = 0.0f;
    }

    // LDS.128 view: each ulonglong2 = two packed (f32x2) j-pairs = 4 j points.
    const ulonglong2* sx4 = reinterpret_cast<const ulonglong2*>(sx);
    const ulonglong2* sy4 = reinterpret_cast<const ulonglong2*>(sy);
    const ulonglong2* sz4 = reinterpret_cast<const ulonglong2*>(sz);

#pragma unroll 2
    for (int jq = 0; jq < TILE / 4; jq++) {
        const ulonglong2 vx = sx4[jq];
        const ulonglong2 vy = sy4[jq];
        const ulonglong2 vz = sz4[jq];
#pragma unroll
        for (int h = 0; h < 2; h++) {
            const u64 njx = (h == 0) ? vx.x : vx.y;
            const u64 njy = (h == 0) ? vy.x : vy.y;
            const u64 njz = (h == 0) ? vz.x : vz.y;
#pragma unroll
            for (int m = 0; m < MI; m++) {
                u64 dx = add2(xip[m], njx);
                u64 dy = add2(yip[m], njy);
                u64 dz = add2(zip[m], njz);
                u64 sq = mul2(dx, dx);
                sq = fma2(dy, dy, sq);
                sq = fma2(dz, dz, sq);
                float s0, s1;
                unpack2(sq, s0, s1);
                const float t0 = fmaxf(r_minus(sqrt_approx(s0), R), 0.0f);
                acc0[m] = fmaf(t0, t0, acc0[m]);
                const float t1 = fmaxf(r_minus(sqrt_approx(s1), R), 0.0f);
                acc1[m] = fmaf(t1, t1, acc1[m]);
            }
        }
    }

    float tot = 0.0f;
#pragma unroll
    for (int m = 0; m < MI; m++) tot += acc0[m] + acc1[m];

    red[tid] = tot;
    __syncthreads();
#pragma unroll
    for (int s = THREADS / 2; s > 0; s >>= 1) {
        if (tid < s) red[tid] += red[tid + s];
        __syncthreads();
    }

    const int part_idx = b * NPAIRT + blockIdx.x;
    if (tid == 0) {
        const float w = (ti == tj) ? 1.0f : 2.0f;
        g_part[part_idx] = red[0] * w;
        __threadfence();
        const unsigned int p = atomicAdd(&g_done, 1u);
        is_last = (p == NPART - 1);
    }
    __syncthreads();

    // Last block performs the fixed-order final reduction (deterministic:
    // the summation order is independent of which block runs it).
    if (is_last) {
        if (tid == 0) g_done = 0;   // reset for the next graph replay
        __threadfence();
        const volatile float* gp = g_part;
        float v = 0.0f;
        for (int i = tid; i < NPART; i += THREADS) v += gp[i];
        red[tid] = v;
        __syncthreads();
#pragma unroll
        for (int s = THREADS / 2; s > 0; s >>= 1) {
            if (tid < s) red[tid] += red[tid + s];
            __syncthreads();
        }
        if (tid == 0) {
            // Each i==i pair contributed exactly (R - sqrt.approx(0))^2 = R^2.
            const float diag = (float)(NBATCH * NPTS) * (RADIUS * RADIUS);
            out[0] = (red[0] - diag) /
                     ((float)NBATCH * (float)NPTS * (float)NPTS);
        }
    }
}

extern "C" void kernel_launch(void* const* d_in, const int* in_sizes, int n_in,
                              void* d_out, int out_size) {
    const float* xyz = (const float*)d_in[0];
    float* out = (float*)d_out;
    (void)in_sizes; (void)n_in; (void)out_size;

    dim3 grid(NPAIRT, NBATCH);
    collreg_kernel<<<grid, THREADS>>>(xyz, out);
}

// round 5
// speedup vs baseline: 1.0124x; 1.0124x over previous
#include <cuda_runtime.h>
#include <cuda_bf16.h>

// CollisionRegularizer: mean over (B,N,N) of relu(R - dist)^2, diagonal masked.
// B=2, N=8192, xyz float32 (B,N,3). Output: 1 float (the mean).
//
// R4 vs R3 (39.3us, occ 11.7%, issue 63%):
//  - TILE 512->256: grid 272 -> 1056 blocks, occ -> ~44% (latency hiding).
//  - Off-diagonal tiles use the Gram identity (|i|^2+|j|^2-2 i.j): 4 packed
//    fma-pipe ops per 2 pairs instead of 6. Diagonal tiles keep the exact
//    direct-difference form so the analytic diagonal subtraction stays exact.
//  - NaN from cancellation (P~1e-10/pair) is absorbed by fmaxf(NaN,0)=0.

#define RADIUS 0.1f
#define NPTS   8192
#define NBATCH 2
#define TILE   256
#define THREADS 128
#define MI     2                              // i-points per thread
#define NTILES (NPTS / TILE)                  // 32
#define NPAIRT (NTILES * (NTILES + 1) / 2)    // 528 tile-pairs per batch
#define NPART  (NBATCH * NPAIRT)              // 1056 blocks / partials

typedef unsigned long long u64;

__device__ __forceinline__ u64 pack2(float lo, float hi) {
    u64 r; asm("mov.b64 %0, {%1, %2};" : "=l"(r) : "f"(lo), "f"(hi)); return r;
}
__device__ __forceinline__ void unpack2(u64 v, float& lo, float& hi) {
    asm("mov.b64 {%0, %1}, %2;" : "=f"(lo), "=f"(hi) : "l"(v));
}
__device__ __forceinline__ u64 add2(u64 a, u64 b) {
    u64 r; asm("add.rn.f32x2 %0, %1, %2;" : "=l"(r) : "l"(a), "l"(b)); return r;
}
__device__ __forceinline__ u64 mul2(u64 a, u64 b) {
    u64 r; asm("mul.rn.f32x2 %0, %1, %2;" : "=l"(r) : "l"(a), "l"(b)); return r;
}
__device__ __forceinline__ u64 fma2(u64 a, u64 b, u64 c) {
    u64 r; asm("fma.rn.f32x2 %0, %1, %2, %3;" : "=l"(r) : "l"(a), "l"(b), "l"(c)); return r;
}
__device__ __forceinline__ float sqrt_approx(float x) {
    float r; asm("sqrt.approx.f32 %0, %1;" : "=f"(r) : "f"(x)); return r;
}
// t = R - d as FFMA with immediate multiplier (-1.0f): rt_SMSP=1 vs FADD's 2.
__device__ __forceinline__ float r_minus(float d, float R) {
    float r; asm("fma.rn.f32 %0, %1, 0fBF800000, %2;" : "=f"(r) : "f"(d), "f"(R)); return r;
}

__device__ float        g_part[NPART];
__device__ unsigned int g_done = 0;

__global__ __launch_bounds__(THREADS)
void collreg_kernel(const float* __restrict__ xyz, float* __restrict__ out) {
    __shared__ __align__(16) float sx[TILE];
    __shared__ __align__(16) float sy[TILE];
    __shared__ __align__(16) float sz[TILE];
    __shared__ __align__(16) float s2[TILE];   // |j|^2
    __shared__ float red[THREADS];
    __shared__ bool  is_last;

    const int tid = threadIdx.x;
    const int b   = blockIdx.y;

    // Decode linear tile-pair index -> (ti, tj), tj >= ti.
    int ti = 0, rem = blockIdx.x;
    while (rem >= NTILES - ti) { rem -= NTILES - ti; ti++; }
    const int tj = ti + rem;

    const float* base = xyz + (size_t)b * NPTS * 3;

    // j tile: plain coords + squared norm, SoA.
    for (int t = tid; t < TILE; t += THREADS) {
        const int j = tj * TILE + t;
        const float x = base[j * 3 + 0];
        const float y = base[j * 3 + 1];
        const float z = base[j * 3 + 2];
        sx[t] = x; sy[t] = y; sz[t] = z;
        s2[t] = x * x + y * y + z * z;
    }
    __syncthreads();

    const float R = RADIUS;

    // i-point data per thread.
    float ix[MI], iy[MI], iz[MI];
#pragma unroll
    for (int m = 0; m < MI; m++) {
        const int i = ti * TILE + tid + m * THREADS;
        ix[m] = base[i * 3 + 0];
        iy[m] = base[i * 3 + 1];
        iz[m] = base[i * 3 + 2];
    }

    float acc0[MI], acc1[MI];
#pragma unroll
    for (int m = 0; m < MI; m++) { acc0[m] = 0.0f; acc1[m] = 0.0f; }

    const ulonglong2* sx4 = reinterpret_cast<const ulonglong2*>(sx);
    const ulonglong2* sy4 = reinterpret_cast<const ulonglong2*>(sy);
    const ulonglong2* sz4 = reinterpret_cast<const ulonglong2*>(sz);
    const ulonglong2* s24 = reinterpret_cast<const ulonglong2*>(s2);

    if (ti != tj) {
        // ---- Gram path: sq = (|i|^2+|j|^2) + (-2xi)xj + (-2yi)yj + (-2zi)zj
        u64 m2x[MI], m2y[MI], m2z[MI], si2[MI];
#pragma unroll
        for (int m = 0; m < MI; m++) {
            m2x[m] = pack2(-2.0f * ix[m], -2.0f * ix[m]);
            m2y[m] = pack2(-2.0f * iy[m], -2.0f * iy[m]);
            m2z[m] = pack2(-2.0f * iz[m], -2.0f * iz[m]);
            const float s = ix[m]*ix[m] + iy[m]*iy[m] + iz[m]*iz[m];
            si2[m] = pack2(s, s);
        }
#pragma unroll 2
        for (int jq = 0; jq < TILE / 4; jq++) {
            const ulonglong2 vx = sx4[jq];
            const ulonglong2 vy = sy4[jq];
            const ulonglong2 vz = sz4[jq];
            const ulonglong2 v2 = s24[jq];
#pragma unroll
            for (int h = 0; h < 2; h++) {
                const u64 jx = (h == 0) ? vx.x : vx.y;
                const u64 jy = (h == 0) ? vy.x : vy.y;
                const u64 jz = (h == 0) ? vz.x : vz.y;
                const u64 j2 = (h == 0) ? v2.x : v2.y;
#pragma unroll
                for (int m = 0; m < MI; m++) {
                    u64 sq = add2(si2[m], j2);
                    sq = fma2(m2x[m], jx, sq);
                    sq = fma2(m2y[m], jy, sq);
                    sq = fma2(m2z[m], jz, sq);
                    float s0, s1;
                    unpack2(sq, s0, s1);
                    const float t0 = fmaxf(r_minus(sqrt_approx(s0), R), 0.0f);
                    acc0[m] = fmaf(t0, t0, acc0[m]);
                    const float t1 = fmaxf(r_minus(sqrt_approx(s1), R), 0.0f);
                    acc1[m] = fmaf(t1, t1, acc1[m]);
                }
            }
        }
    } else {
        // ---- Diagonal-tile path: exact direct differences ((-i) + j).
        u64 nx[MI], ny[MI], nz[MI];
#pragma unroll
        for (int m = 0; m < MI; m++) {
            nx[m] = pack2(-ix[m], -ix[m]);
            ny[m] = pack2(-iy[m], -iy[m]);
            nz[m] = pack2(-iz[m], -iz[m]);
        }
#pragma unroll 2
        for (int jq = 0; jq < TILE / 4; jq++) {
            const ulonglong2 vx = sx4[jq];
            const ulonglong2 vy = sy4[jq];
            const ulonglong2 vz = sz4[jq];
#pragma unroll
            for (int h = 0; h < 2; h++) {
                const u64 jx = (h == 0) ? vx.x : vx.y;
                const u64 jy = (h == 0) ? vy.x : vy.y;
                const u64 jz = (h == 0) ? vz.x : vz.y;
#pragma unroll
                for (int m = 0; m < MI; m++) {
                    u64 dx = add2(nx[m], jx);
                    u64 dy = add2(ny[m], jy);
                    u64 dz = add2(nz[m], jz);
                    u64 sq = mul2(dx, dx);
                    sq = fma2(dy, dy, sq);
                    sq = fma2(dz, dz, sq);
                    float s0, s1;
                    unpack2(sq, s0, s1);
                    const float t0 = fmaxf(r_minus(sqrt_approx(s0), R), 0.0f);
                    acc0[m] = fmaf(t0, t0, acc0[m]);
                    const float t1 = fmaxf(r_minus(sqrt_approx(s1), R), 0.0f);
                    acc1[m] = fmaf(t1, t1, acc1[m]);
                }
            }
        }
    }

    float tot = 0.0f;
#pragma unroll
    for (int m = 0; m < MI; m++) tot += acc0[m] + acc1[m];

    red[tid] = tot;
    __syncthreads();
#pragma unroll
    for (int s = THREADS / 2; s > 0; s >>= 1) {
        if (tid < s) red[tid] += red[tid + s];
        __syncthreads();
    }

    const int part_idx = b * NPAIRT + blockIdx.x;
    if (tid == 0) {
        const float w = (ti == tj) ? 1.0f : 2.0f;
        g_part[part_idx] = red[0] * w;
        __threadfence();
        const unsigned int p = atomicAdd(&g_done, 1u);
        is_last = (p == NPART - 1);
    }
    __syncthreads();

    // Last block: fixed-order final reduction (deterministic regardless of
    // which block runs it).
    if (is_last) {
        if (tid == 0) g_done = 0;   // reset for next graph replay
        __threadfence();
        const volatile float* gp = g_part;
        float v = 0.0f;
        for (int i = tid; i < NPART; i += THREADS) v += gp[i];
        red[tid] = v;
        __syncthreads();
#pragma unroll
        for (int s = THREADS / 2; s > 0; s >>= 1) {
            if (tid < s) red[tid] += red[tid + s];
            __syncthreads();
        }
        if (tid == 0) {
            // Diagonal pairs (exact path) each contributed exactly R^2.
            const float diag = (float)(NBATCH * NPTS) * (RADIUS * RADIUS);
            out[0] = (red[0] - diag) /
                     ((float)NBATCH * (float)NPTS * (float)NPTS);
        }
    }
}

extern "C" void kernel_launch(void* const* d_in, const int* in_sizes, int n_in,
                              void* d_out, int out_size) {
    const float* xyz = (const float*)d_in[0];
    float* out = (float*)d_out;
    (void)in_sizes; (void)n_in; (void)out_size;

    dim3 grid(NPAIRT, NBATCH);
    collreg_kernel<<<grid, THREADS>>>(xyz, out);
}

// round 6
// speedup vs baseline: 1.0514x; 1.0386x over previous
#include <cuda_runtime.h>
#include <cuda_bf16.h>

// CollisionRegularizer: mean over (B,N,N) of relu(R - dist)^2, diagonal masked.
// B=2, N=8192, xyz float32 (B,N,3). Output: 1 float (the mean).
//
// R4 vs R3 (39.3us, occ 11.7%, issue 63%):
//  - TILE 512->256: grid 272 -> 1056 blocks, occ -> ~44% (latency hiding).
//  - Off-diagonal tiles use the Gram identity (|i|^2+|j|^2-2 i.j): 4 packed
//    fma-pipe ops per 2 pairs instead of 6. Diagonal tiles keep the exact
//    direct-difference form so the analytic diagonal subtraction stays exact.
//  - NaN from cancellation (P~1e-10/pair) is absorbed by fmaxf(NaN,0)=0.

#define RADIUS 0.1f
#define NPTS   8192
#define NBATCH 2
#define TILE   256
#define THREADS 128
#define MI     2                              // i-points per thread
#define NTILES (NPTS / TILE)                  // 32
#define NPAIRT (NTILES * (NTILES + 1) / 2)    // 528 tile-pairs per batch
#define NPART  (NBATCH * NPAIRT)              // 1056 blocks / partials

typedef unsigned long long u64;

__device__ __forceinline__ u64 pack2(float lo, float hi) {
    u64 r; asm("mov.b64 %0, {%1, %2};" : "=l"(r) : "f"(lo), "f"(hi)); return r;
}
__device__ __forceinline__ void unpack2(u64 v, float& lo, float& hi) {
    asm("mov.b64 {%0, %1}, %2;" : "=f"(lo), "=f"(hi) : "l"(v));
}
__device__ __forceinline__ u64 add2(u64 a, u64 b) {
    u64 r; asm("add.rn.f32x2 %0, %1, %2;" : "=l"(r) : "l"(a), "l"(b)); return r;
}
__device__ __forceinline__ u64 mul2(u64 a, u64 b) {
    u64 r; asm("mul.rn.f32x2 %0, %1, %2;" : "=l"(r) : "l"(a), "l"(b)); return r;
}
__device__ __forceinline__ u64 fma2(u64 a, u64 b, u64 c) {
    u64 r; asm("fma.rn.f32x2 %0, %1, %2, %3;" : "=l"(r) : "l"(a), "l"(b), "l"(c)); return r;
}
__device__ __forceinline__ float sqrt_approx(float x) {
    float r; asm("sqrt.approx.f32 %0, %1;" : "=f"(r) : "f"(x)); return r;
}
// t = R - d as FFMA with immediate multiplier (-1.0f): rt_SMSP=1 vs FADD's 2.
__device__ __forceinline__ float r_minus(float d, float R) {
    float r; asm("fma.rn.f32 %0, %1, 0fBF800000, %2;" : "=f"(r) : "f"(d), "f"(R)); return r;
}

__device__ float        g_part[NPART];
__device__ unsigned int g_done = 0;

__global__ __launch_bounds__(THREADS)
void collreg_kernel(const float* __restrict__ xyz, float* __restrict__ out) {
    __shared__ __align__(16) float sx[TILE];
    __shared__ __align__(16) float sy[TILE];
    __shared__ __align__(16) float sz[TILE];
    __shared__ __align__(16) float s2[TILE];   // |j|^2
    __shared__ float red[THREADS];
    __shared__ bool  is_last;

    const int tid = threadIdx.x;
    const int b   = blockIdx.y;

    // Decode linear tile-pair index -> (ti, tj), tj >= ti.
    int ti = 0, rem = blockIdx.x;
    while (rem >= NTILES - ti) { rem -= NTILES - ti; ti++; }
    const int tj = ti + rem;

    const float* base = xyz + (size_t)b * NPTS * 3;

    // j tile: plain coords + squared norm, SoA.
    for (int t = tid; t < TILE; t += THREADS) {
        const int j = tj * TILE + t;
        const float x = base[j * 3 + 0];
        const float y = base[j * 3 + 1];
        const float z = base[j * 3 + 2];
        sx[t] = x; sy[t] = y; sz[t] = z;
        s2[t] = x * x + y * y + z * z;
    }
    __syncthreads();

    const float R = RADIUS;

    // i-point data per thread.
    float ix[MI], iy[MI], iz[MI];
#pragma unroll
    for (int m = 0; m < MI; m++) {
        const int i = ti * TILE + tid + m * THREADS;
        ix[m] = base[i * 3 + 0];
        iy[m] = base[i * 3 + 1];
        iz[m] = base[i * 3 + 2];
    }

    float acc0[MI], acc1[MI];
#pragma unroll
    for (int m = 0; m < MI; m++) { acc0[m] = 0.0f; acc1[m] = 0.0f; }

    const ulonglong2* sx4 = reinterpret_cast<const ulonglong2*>(sx);
    const ulonglong2* sy4 = reinterpret_cast<const ulonglong2*>(sy);
    const ulonglong2* sz4 = reinterpret_cast<const ulonglong2*>(sz);
    const ulonglong2* s24 = reinterpret_cast<const ulonglong2*>(s2);

    if (ti != tj) {
        // ---- Gram path: sq = (|i|^2+|j|^2) + (-2xi)xj + (-2yi)yj + (-2zi)zj
        u64 m2x[MI], m2y[MI], m2z[MI], si2[MI];
#pragma unroll
        for (int m = 0; m < MI; m++) {
            m2x[m] = pack2(-2.0f * ix[m], -2.0f * ix[m]);
            m2y[m] = pack2(-2.0f * iy[m], -2.0f * iy[m]);
            m2z[m] = pack2(-2.0f * iz[m], -2.0f * iz[m]);
            const float s = ix[m]*ix[m] + iy[m]*iy[m] + iz[m]*iz[m];
            si2[m] = pack2(s, s);
        }
#pragma unroll 2
        for (int jq = 0; jq < TILE / 4; jq++) {
            const ulonglong2 vx = sx4[jq];
            const ulonglong2 vy = sy4[jq];
            const ulonglong2 vz = sz4[jq];
            const ulonglong2 v2 = s24[jq];
#pragma unroll
            for (int h = 0; h < 2; h++) {
                const u64 jx = (h == 0) ? vx.x : vx.y;
                const u64 jy = (h == 0) ? vy.x : vy.y;
                const u64 jz = (h == 0) ? vz.x : vz.y;
                const u64 j2 = (h == 0) ? v2.x : v2.y;
#pragma unroll
                for (int m = 0; m < MI; m++) {
                    u64 sq = add2(si2[m], j2);
                    sq = fma2(m2x[m], jx, sq);
                    sq = fma2(m2y[m], jy, sq);
                    sq = fma2(m2z[m], jz, sq);
                    float s0, s1;
                    unpack2(sq, s0, s1);
                    const float t0 = fmaxf(r_minus(sqrt_approx(s0), R), 0.0f);
                    acc0[m] = fmaf(t0, t0, acc0[m]);
                    const float t1 = fmaxf(r_minus(sqrt_approx(s1), R), 0.0f);
                    acc1[m] = fmaf(t1, t1, acc1[m]);
                }
            }
        }
    } else {
        // ---- Diagonal-tile path: exact direct differences ((-i) + j).
        u64 nx[MI], ny[MI], nz[MI];
#pragma unroll
        for (int m = 0; m < MI; m++) {
            nx[m] = pack2(-ix[m], -ix[m]);
            ny[m] = pack2(-iy[m], -iy[m]);
            nz[m] = pack2(-iz[m], -iz[m]);
        }
#pragma unroll 2
        for (int jq = 0; jq < TILE / 4; jq++) {
            const ulonglong2 vx = sx4[jq];
            const ulonglong2 vy = sy4[jq];
            const ulonglong2 vz = sz4[jq];
#pragma unroll
            for (int h = 0; h < 2; h++) {
                const u64 jx = (h == 0) ? vx.x : vx.y;
                const u64 jy = (h == 0) ? vy.x : vy.y;
                const u64 jz = (h == 0) ? vz.x : vz.y;
#pragma unroll
                for (int m = 0; m < MI; m++) {
                    u64 dx = add2(nx[m], jx);
                    u64 dy = add2(ny[m], jy);
                    u64 dz = add2(nz[m], jz);
                    u64 sq = mul2(dx, dx);
                    sq = fma2(dy, dy, sq);
                    sq = fma2(dz, dz, sq);
                    float s0, s1;
                    unpack2(sq, s0, s1);
                    const float t0 = fmaxf(r_minus(sqrt_approx(s0), R), 0.0f);
                    acc0[m] = fmaf(t0, t0, acc0[m]);
                    const float t1 = fmaxf(r_minus(sqrt_approx(s1), R), 0.0f);
                    acc1[m] = fmaf(t1, t1, acc1[m]);
                }
            }
        }
    }

    float tot = 0.0f;
#pragma unroll
    for (int m = 0; m < MI; m++) tot += acc0[m] + acc1[m];

    red[tid] = tot;
    __syncthreads();
#pragma unroll
    for (int s = THREADS / 2; s > 0; s >>= 1) {
        if (tid < s) red[tid] += red[tid + s];
        __syncthreads();
    }

    const int part_idx = b * NPAIRT + blockIdx.x;
    if (tid == 0) {
        const float w = (ti == tj) ? 1.0f : 2.0f;
        g_part[part_idx] = red[0] * w;
        __threadfence();
        const unsigned int p = atomicAdd(&g_done, 1u);
        is_last = (p == NPART - 1);
    }
    __syncthreads();

    // Last block: fixed-order final reduction (deterministic regardless of
    // which block runs it).
    if (is_last) {
        if (tid == 0) g_done = 0;   // reset for next graph replay
        __threadfence();
        const volatile float* gp = g_part;
        float v = 0.0f;
        for (int i = tid; i < NPART; i += THREADS) v += gp[i];
        red[tid] = v;
        __syncthreads();
#pragma unroll
        for (int s = THREADS / 2; s > 0; s >>= 1) {
            if (tid < s) red[tid] += red[tid + s];
            __syncthreads();
        }
        if (tid == 0) {
            // Diagonal pairs (exact path) each contributed exactly R^2.
            const float diag = (float)(NBATCH * NPTS) * (RADIUS * RADIUS);
            out[0] = (red[0] - diag) /
                     ((float)NBATCH * (float)NPTS * (float)NPTS);
        }
    }
}

extern "C" void kernel_launch(void* const* d_in, const int* in_sizes, int n_in,
                              void* d_out, int out_size) {
    const float* xyz = (const float*)d_in[0];
    float* out = (float*)d_out;
    (void)in_sizes; (void)n_in; (void)out_size;

    dim3 grid(NPAIRT, NBATCH);
    collreg_kernel<<<grid, THREADS>>>(xyz, out);
}